// round 14
// baseline (speedup 1.0000x reference)
#include <cuda_runtime.h>
#include <cstdint>

typedef unsigned long long ull;

// Problem constants
constexpr int B_TOT = 16384;
constexpr int F = 40;
constexpr int D = 32;
constexpr int FD = F * D;              // 1280
constexpr int NB = 16;                 // batches per CTA
constexpr int GRID = B_TOT / NB;       // 1024
constexpr int NTHREADS = 768;          // 24 warps

// Shared strides (floats)
constexpr int HSTR  = 1284;            // h rows       (mod 32 == 4)
constexpr int HOSTR = 1444;            // hout/aggr    (mod 32 == 4)
constexpr int GSTR  = 1600;            // g rows (natural)
constexpr int AFS   = 36;              // aggr f-stride (mod 32 == 4)

// smem offsets (floats)
constexpr int OH  = 0;                     // h:    16*1284 = 20544
constexpr int OHO = OH + NB * HSTR;        // ho:   16*1444 = 23104
constexpr int OG  = OHO + NB * HOSTR;      // g:     8*1600 = 12800
constexpr int OMB = OG + 8 * GSTR;         // mbarriers (3 x u64)
constexpr int SMEM_BYTES = (OMB + 8) * 4;  // 225824 B

// Fragment-ordered W (hi, lo) pairs: [w(out=0,in=1)][f][kt][nt][r][lane]
__device__ float2 g_Wfrag[2 * 40 * 4 * 4 * 2 * 32];

// ---------------- helpers ----------------
__device__ __forceinline__ ull pack2(float v) {
    ull r;
    asm("mov.b64 %0, {%1, %1};" : "=l"(r) : "f"(v));
    return r;
}
__device__ __forceinline__ ull packf(float lo, float hi) {
    ull r;
    asm("mov.b64 %0, {%1, %2};" : "=l"(r) : "f"(lo), "f"(hi));
    return r;
}
__device__ __forceinline__ ull ffma2(ull a, ull b, ull c) {
    ull d;
    asm("fma.rn.f32x2 %0, %1, %2, %3;" : "=l"(d) : "l"(a), "l"(b), "l"(c));
    return d;
}
__device__ __forceinline__ uint32_t cvt_tf32(float x) {
    uint32_t u;
    asm("cvt.rna.tf32.f32 %0, %1;" : "=r"(u) : "f"(x));
    return u;
}
// D(16x8) += A(16x8,row) * B(8x8,col), tf32 inputs as b32 regs, f32 accum
__device__ __forceinline__ void mma_tf32(float* d,
                                         uint32_t a0, uint32_t a1, uint32_t a2, uint32_t a3,
                                         uint32_t b0, uint32_t b1) {
    asm volatile(
        "mma.sync.aligned.m16n8k8.row.col.f32.tf32.tf32.f32 "
        "{%0,%1,%2,%3}, {%4,%5,%6,%7}, {%8,%9}, {%0,%1,%2,%3};"
        : "+f"(d[0]), "+f"(d[1]), "+f"(d[2]), "+f"(d[3])
        : "r"(a0), "r"(a1), "r"(a2), "r"(a3), "r"(b0), "r"(b1));
}
__device__ __forceinline__ uint32_t smem_u32(const void* p) {
    return (uint32_t)__cvta_generic_to_shared(p);
}
__device__ __forceinline__ void mbar_init(uint32_t mbar, uint32_t cnt) {
    asm volatile("mbarrier.init.shared.b64 [%0], %1;" :: "r"(mbar), "r"(cnt) : "memory");
}
__device__ __forceinline__ void mbar_expect_tx(uint32_t mbar, uint32_t bytes) {
    asm volatile("mbarrier.arrive.expect_tx.shared.b64 _, [%0], %1;"
                 :: "r"(mbar), "r"(bytes) : "memory");
}
__device__ __forceinline__ void mbar_wait(uint32_t mbar, uint32_t parity) {
    uint32_t done;
    asm volatile(
        "{\n\t.reg .pred p;\n\t"
        "mbarrier.try_wait.parity.acquire.cta.shared::cta.b64 p, [%1], %2;\n\t"
        "selp.b32 %0, 1, 0, p;\n\t}"
        : "=r"(done) : "r"(mbar), "r"(parity) : "memory");
    if (!done) {
        asm volatile(
            "{\n\t.reg .pred P1;\n\t"
            "W_%=:\n\t"
            "mbarrier.try_wait.parity.acquire.cta.shared::cta.b64 P1, [%0], %1, 0x989680;\n\t"
            "@P1 bra.uni DONE_%=;\n\t"
            "bra.uni W_%=;\n\t"
            "DONE_%=:\n\t}"
            :: "r"(mbar), "r"(parity) : "memory");
    }
}
__device__ __forceinline__ void bulk_copy(uint32_t dst_smem, const void* src,
                                          uint32_t bytes, uint32_t mbar) {
    asm volatile(
        "cp.async.bulk.shared::cluster.global.mbarrier::complete_tx::bytes "
        "[%0], [%1], %2, [%3];"
        :: "r"(dst_smem), "l"(src), "r"(bytes), "r"(mbar) : "memory");
}

// ---------------- W fragment-build prologue ----------------
// One block per (w, f). W[f][d][e] row-major. Fragment element:
//   d = nt*8 + (lane>>2), e = kt*8 + (lane&3) + 4*r
__global__ void __launch_bounds__(1024)
buildWfrag_kernel(const float* __restrict__ W_in, const float* __restrict__ W_out)
{
    const int blk = blockIdx.x;             // 0..79
    const int w = blk / 40;                 // 0 = Wout (stage1), 1 = Win (stage3)
    const int f = blk % 40;
    const float* src = (w == 0) ? W_out : W_in;

    const int t    = threadIdx.x;
    const int kt   = (t >> 8) & 3;
    const int nt   = (t >> 6) & 3;
    const int r    = (t >> 5) & 1;
    const int lane = t & 31;

    const int d = nt * 8 + (lane >> 2);
    const int e = kt * 8 + (lane & 3) + 4 * r;
    const float v = src[f * 1024 + d * 32 + e];
    const float hi = __uint_as_float(cvt_tf32(v));
    const float lo = __uint_as_float(cvt_tf32(v - hi));
    g_Wfrag[((((w * 40 + f) * 4 + kt) * 4 + nt) * 2 + r) * 32 + lane] =
        make_float2(hi, lo);
}

// ---------------- main fused kernel ----------------
__global__ void __launch_bounds__(NTHREADS, 1)
graphlayer_kernel(const float* __restrict__ g,
                  const float* __restrict__ h,
                  const float* __restrict__ bias_p,
                  float* __restrict__ out)
{
    extern __shared__ float smem[];
    float* h_s  = smem + OH;
    float* hoag = smem + OHO;
    float* g_s  = smem + OG;

    const int tid  = threadIdx.x;
    const int lane = tid & 31;
    const int warp = tid >> 5;          // 0..23
    const long b0  = (long)blockIdx.x * NB;

    const uint32_t mb_h  = smem_u32(smem + OMB);
    const uint32_t mb_g1 = mb_h + 8;
    const uint32_t mb_g2 = mb_h + 16;

    if (tid == 0) {
        mbar_init(mb_h, 1);
        mbar_init(mb_g1, 1);
        mbar_init(mb_g2, 1);
    }
    __syncthreads();

    if (tid == 0) {
        mbar_expect_tx(mb_h, NB * FD * 4);
        const uint32_t hdst = smem_u32(h_s);
        #pragma unroll
        for (int j = 0; j < NB; j++)
            bulk_copy(hdst + j * HSTR * 4, h + (b0 + j) * FD, FD * 4, mb_h);
        mbar_expect_tx(mb_g1, 8 * F * F * 4);
        const uint32_t gdst = smem_u32(g_s);
        #pragma unroll
        for (int j = 0; j < 8; j++)
            bulk_copy(gdst + j * GSTR * 4, g + (b0 + j) * (F * F), F * F * 4, mb_g1);
    }

    const int grp = lane >> 2;          // 0..7 (j row low / n col)
    const int qid = lane & 3;           // 0..3

    mbar_wait(mb_h, 0);

    // ---------------- Stage 1 (tensor): hout[j][f][:] = h[j][f][:] @ Wout[f]^T ----------
    // One warp per f: D[16x32] = A[16x32] * B[32x32], 4 k-tiles x 4 n-tiles.
    #pragma unroll 1
    for (int f = warp; f < F; f += 24) {
        float acc[4][4] = {};
        const float2* wb = g_Wfrag + (((0 * 40 + f) * 4) * 4) * 2 * 32 + lane;
        #pragma unroll
        for (int kt = 0; kt < 4; kt++) {
            const float* ab = h_s + f * 32 + kt * 8 + qid;
            const float a0 = ab[grp * HSTR];
            const float a1 = ab[(grp + 8) * HSTR];
            const float a2 = ab[grp * HSTR + 4];
            const float a3 = ab[(grp + 8) * HSTR + 4];
            const uint32_t ah0 = cvt_tf32(a0), ah1 = cvt_tf32(a1),
                           ah2 = cvt_tf32(a2), ah3 = cvt_tf32(a3);
            const uint32_t al0 = cvt_tf32(a0 - __uint_as_float(ah0));
            const uint32_t al1 = cvt_tf32(a1 - __uint_as_float(ah1));
            const uint32_t al2 = cvt_tf32(a2 - __uint_as_float(ah2));
            const uint32_t al3 = cvt_tf32(a3 - __uint_as_float(ah3));
            #pragma unroll
            for (int nt = 0; nt < 4; nt++) {
                const float2 B0 = __ldg(wb + ((kt * 4 + nt) * 2 + 0) * 32);
                const float2 B1 = __ldg(wb + ((kt * 4 + nt) * 2 + 1) * 32);
                const uint32_t bh0 = __float_as_uint(B0.x), bh1 = __float_as_uint(B1.x);
                const uint32_t bl0 = __float_as_uint(B0.y), bl1 = __float_as_uint(B1.y);
                mma_tf32(acc[nt], ah0, ah1, ah2, ah3, bh0, bh1);
                mma_tf32(acc[nt], ah0, ah1, ah2, ah3, bl0, bl1);
                mma_tf32(acc[nt], al0, al1, al2, al3, bh0, bh1);
            }
        }
        #pragma unroll
        for (int nt = 0; nt < 4; nt++) {
            *(ull*)&hoag[grp * HOSTR + f * 32 + nt * 8 + 2 * qid] =
                packf(acc[nt][0], acc[nt][1]);
            *(ull*)&hoag[(grp + 8) * HOSTR + f * 32 + nt * 8 + 2 * qid] =
                packf(acc[nt][2], acc[nt][3]);
        }
    }
    __syncthreads();

    // prefetch g chunk 2 (j = 8..15) into the (now free) h region
    if (tid == 0) {
        mbar_expect_tx(mb_g2, 8 * F * F * 4);
        const uint32_t gdst2 = smem_u32(h_s);
        #pragma unroll
        for (int j = 0; j < 8; j++)
            bulk_copy(gdst2 + j * GSTR * 4, g + (b0 + 8 + j) * (F * F), F * F * 4, mb_g2);
    }

    // ---------------- Stage 2 (fp32): aggr[j][f][d] = sum_gi g[j][f][gi] hout[j][gi][d]
    if (warp < NB) {
        const int j = warp;
        if (j < 8) mbar_wait(mb_g1, 0);
        else       mbar_wait(mb_g2, 0);
        const float* gj  = (j < 8) ? (g_s + j * GSTR) : (h_s + (j - 8) * GSTR);
        float*       hob = hoag + j * HOSTR;
        const int fg = lane >> 3;
        const int dm = lane & 7;

        ull acc[10][2];
        #pragma unroll
        for (int ft = 0; ft < 10; ft++) { acc[ft][0] = 0ull; acc[ft][1] = 0ull; }

        #pragma unroll 2
        for (int gp = 0; gp < 10; gp++) {          // 4 gi per iter
            ull ho0[4], ho1[4];
            #pragma unroll
            for (int t = 0; t < 4; t++) {
                ho0[t] = *(const ull*)(hob + (gp * 4 + t) * 32 + dm * 2);
                ho1[t] = *(const ull*)(hob + (gp * 4 + t) * 32 + dm * 2 + 16);
            }
            #pragma unroll
            for (int ft = 0; ft < 10; ft++) {
                const float4 g4 = *(const float4*)(gj + (fg + 4 * ft) * F + gp * 4);
                acc[ft][0] = ffma2(pack2(g4.x), ho0[0], acc[ft][0]);
                acc[ft][1] = ffma2(pack2(g4.x), ho1[0], acc[ft][1]);
                acc[ft][0] = ffma2(pack2(g4.y), ho0[1], acc[ft][0]);
                acc[ft][1] = ffma2(pack2(g4.y), ho1[1], acc[ft][1]);
                acc[ft][0] = ffma2(pack2(g4.z), ho0[2], acc[ft][0]);
                acc[ft][1] = ffma2(pack2(g4.z), ho1[2], acc[ft][1]);
                acc[ft][0] = ffma2(pack2(g4.w), ho0[3], acc[ft][0]);
                acc[ft][1] = ffma2(pack2(g4.w), ho1[3], acc[ft][1]);
            }
        }
        #pragma unroll
        for (int ft = 0; ft < 10; ft++) {
            const int f = fg + 4 * ft;
            *(ull*)(hob + f * AFS + dm * 2)      = acc[ft][0];
            *(ull*)(hob + f * AFS + dm * 2 + 16) = acc[ft][1];
        }
    }
    __syncthreads();

    // ---------------- Stage 3 (tensor): out[j][f][:] = aggr[j][f][:] @ Win[f]^T + bias
    #pragma unroll 1
    for (int f = warp; f < F; f += 24) {
        float acc[4][4];
        #pragma unroll
        for (int nt = 0; nt < 4; nt++) {
            const float2 bv = __ldg((const float2*)(bias_p + nt * 8 + 2 * qid));
            acc[nt][0] = bv.x; acc[nt][1] = bv.y;
            acc[nt][2] = bv.x; acc[nt][3] = bv.y;
        }
        const float2* wb = g_Wfrag + (((1 * 40 + f) * 4) * 4) * 2 * 32 + lane;
        #pragma unroll
        for (int kt = 0; kt < 4; kt++) {
            const float* ab = hoag + f * AFS + kt * 8 + qid;
            const float a0 = ab[grp * HOSTR];
            const float a1 = ab[(grp + 8) * HOSTR];
            const float a2 = ab[grp * HOSTR + 4];
            const float a3 = ab[(grp + 8) * HOSTR + 4];
            const uint32_t ah0 = cvt_tf32(a0), ah1 = cvt_tf32(a1),
                           ah2 = cvt_tf32(a2), ah3 = cvt_tf32(a3);
            const uint32_t al0 = cvt_tf32(a0 - __uint_as_float(ah0));
            const uint32_t al1 = cvt_tf32(a1 - __uint_as_float(ah1));
            const uint32_t al2 = cvt_tf32(a2 - __uint_as_float(ah2));
            const uint32_t al3 = cvt_tf32(a3 - __uint_as_float(ah3));
            #pragma unroll
            for (int nt = 0; nt < 4; nt++) {
                const float2 B0 = __ldg(wb + ((kt * 4 + nt) * 2 + 0) * 32);
                const float2 B1 = __ldg(wb + ((kt * 4 + nt) * 2 + 1) * 32);
                const uint32_t bh0 = __float_as_uint(B0.x), bh1 = __float_as_uint(B1.x);
                const uint32_t bl0 = __float_as_uint(B0.y), bl1 = __float_as_uint(B1.y);
                mma_tf32(acc[nt], ah0, ah1, ah2, ah3, bh0, bh1);
                mma_tf32(acc[nt], ah0, ah1, ah2, ah3, bl0, bl1);
                mma_tf32(acc[nt], al0, al1, al2, al3, bh0, bh1);
            }
        }
        #pragma unroll
        for (int nt = 0; nt < 4; nt++) {
            *(ull*)&out[(b0 + grp) * FD + f * 32 + nt * 8 + 2 * qid] =
                packf(acc[nt][0], acc[nt][1]);
            *(ull*)&out[(b0 + grp + 8) * FD + f * 32 + nt * 8 + 2 * qid] =
                packf(acc[nt][2], acc[nt][3]);
        }
    }
}

extern "C" void kernel_launch(void* const* d_in, const int* in_sizes, int n_in,
                              void* d_out, int out_size)
{
    (void)in_sizes; (void)n_in; (void)out_size;
    const float* g     = (const float*)d_in[0];
    const float* h     = (const float*)d_in[1];
    const float* W_in  = (const float*)d_in[2];
    const float* W_out = (const float*)d_in[3];
    const float* bias  = (const float*)d_in[4];
    float* out = (float*)d_out;

    cudaFuncSetAttribute(graphlayer_kernel,
                         cudaFuncAttributeMaxDynamicSharedMemorySize, SMEM_BYTES);

    buildWfrag_kernel<<<80, 1024>>>(W_in, W_out);
    graphlayer_kernel<<<GRID, NTHREADS, SMEM_BYTES>>>(g, h, bias, out);
}

// round 15
// speedup vs baseline: 1.3042x; 1.3042x over previous
#include <cuda_runtime.h>
#include <cstdint>

typedef unsigned long long ull;

// Problem constants
constexpr int B_TOT = 16384;
constexpr int F = 40;
constexpr int D = 32;
constexpr int FD = F * D;              // 1280
constexpr int NB = 16;                 // batches per CTA
constexpr int GRID = B_TOT / NB;       // 1024
constexpr int NTHREADS = 640;          // 20 warps

// Shared strides (floats)
constexpr int HSTR  = 1284;            // h rows       (mod 32 == 4)
constexpr int HOSTR = 1444;            // hout/aggr    (mod 32 == 4)
constexpr int GSTR  = 1600;            // g rows (natural)
constexpr int AFS   = 36;              // aggr f-stride (mod 32 == 4)

// smem offsets (floats)
constexpr int OH  = 0;                     // h:    16*1284 = 20544
constexpr int OHO = OH + NB * HSTR;        // ho:   16*1444 = 23104
constexpr int OG  = OHO + NB * HOSTR;      // g:     8*1600 = 12800
constexpr int OMB = OG + 8 * GSTR;         // mbarriers (3 x u64)
constexpr int SMEM_BYTES = (OMB + 8) * 4;  // 225824 B

// W transpose scratch: [0..40) Wout_t, [40..80) Win_t, each [f][e][d]
__device__ float g_Wt[2 * 40 * 1024];

// ---------------- helpers ----------------
__device__ __forceinline__ ull pack2(float v) {
    ull r;
    asm("mov.b64 %0, {%1, %1};" : "=l"(r) : "f"(v));
    return r;
}
__device__ __forceinline__ ull packf(float lo, float hi) {
    ull r;
    asm("mov.b64 %0, {%1, %2};" : "=l"(r) : "f"(lo), "f"(hi));
    return r;
}
__device__ __forceinline__ ull ffma2(ull a, ull b, ull c) {
    ull d;
    asm("fma.rn.f32x2 %0, %1, %2, %3;" : "=l"(d) : "l"(a), "l"(b), "l"(c));
    return d;
}
__device__ __forceinline__ uint32_t smem_u32(const void* p) {
    return (uint32_t)__cvta_generic_to_shared(p);
}
__device__ __forceinline__ void mbar_init(uint32_t mbar, uint32_t cnt) {
    asm volatile("mbarrier.init.shared.b64 [%0], %1;" :: "r"(mbar), "r"(cnt) : "memory");
}
__device__ __forceinline__ void mbar_expect_tx(uint32_t mbar, uint32_t bytes) {
    asm volatile("mbarrier.arrive.expect_tx.shared.b64 _, [%0], %1;"
                 :: "r"(mbar), "r"(bytes) : "memory");
}
__device__ __forceinline__ void mbar_wait(uint32_t mbar, uint32_t parity) {
    uint32_t done;
    asm volatile(
        "{\n\t.reg .pred p;\n\t"
        "mbarrier.try_wait.parity.acquire.cta.shared::cta.b64 p, [%1], %2;\n\t"
        "selp.b32 %0, 1, 0, p;\n\t}"
        : "=r"(done) : "r"(mbar), "r"(parity) : "memory");
    if (!done) {
        asm volatile(
            "{\n\t.reg .pred P1;\n\t"
            "W_%=:\n\t"
            "mbarrier.try_wait.parity.acquire.cta.shared::cta.b64 P1, [%0], %1, 0x989680;\n\t"
            "@P1 bra.uni DONE_%=;\n\t"
            "bra.uni W_%=;\n\t"
            "DONE_%=:\n\t}"
            :: "r"(mbar), "r"(parity) : "memory");
    }
}
__device__ __forceinline__ void bulk_copy(uint32_t dst_smem, const void* src,
                                          uint32_t bytes, uint32_t mbar) {
    asm volatile(
        "cp.async.bulk.shared::cluster.global.mbarrier::complete_tx::bytes "
        "[%0], [%1], %2, [%3];"
        :: "r"(dst_smem), "l"(src), "r"(bytes), "r"(mbar) : "memory");
}

// ---------------- W transpose prologue ----------------
__global__ void __launch_bounds__(1024)
transposeW_kernel(const float* __restrict__ W_in, const float* __restrict__ W_out)
{
    __shared__ float t[32][33];
    const int b = blockIdx.x;                         // 0..79
    const float* src = (b < 40) ? (W_out + b * 1024) : (W_in + (b - 40) * 1024);
    float* dst = g_Wt + b * 1024;
    const int c = threadIdx.x & 31;
    const int r = threadIdx.x >> 5;
    t[r][c] = src[r * 32 + c];       // t[d][e] = W[d][e]
    __syncthreads();
    dst[r * 32 + c] = t[c][r];       // Wt[e][d] = W[d][e]
}

// ---------------- main fused kernel ----------------
__global__ void __launch_bounds__(NTHREADS, 1)
graphlayer_kernel(const float* __restrict__ g,
                  const float* __restrict__ h,
                  const float* __restrict__ bias_p,
                  float* __restrict__ out)
{
    extern __shared__ float smem[];
    float* h_s  = smem + OH;
    float* hoag = smem + OHO;
    float* g_s  = smem + OG;

    const int tid  = threadIdx.x;
    const int lane = tid & 31;
    const int warp = tid >> 5;          // 0..19
    const long b0  = (long)blockIdx.x * NB;

    const uint32_t mb_h  = smem_u32(smem + OMB);
    const uint32_t mb_g1 = mb_h + 8;
    const uint32_t mb_g2 = mb_h + 16;

    if (tid == 0) {
        mbar_init(mb_h, 1);
        mbar_init(mb_g1, 1);
        mbar_init(mb_g2, 1);
    }
    __syncthreads();

    if (tid == 0) {
        mbar_expect_tx(mb_h, NB * FD * 4);
        const uint32_t hdst = smem_u32(h_s);
        #pragma unroll
        for (int j = 0; j < NB; j++)
            bulk_copy(hdst + j * HSTR * 4, h + (b0 + j) * FD, FD * 4, mb_h);
        mbar_expect_tx(mb_g1, 8 * F * F * 4);
        const uint32_t gdst = smem_u32(g_s);
        #pragma unroll
        for (int j = 0; j < 8; j++)
            bulk_copy(gdst + j * GSTR * 4, g + (b0 + j) * (F * F), F * F * 4, mb_g1);
    }

    const float* WoutT = g_Wt;
    const float* WinT  = g_Wt + 40 * 1024;

    const int jg = lane >> 2;           // 0..7 (j rows: jg, jg+8)
    const int dg = lane & 3;            // 0..3 (d-octet: dg*8 .. dg*8+7)

    mbar_wait(mb_h, 0);

    // ---------------- Stage 1: hout[j][f][d] = sum_e Wout[f][d][e] h[j][f][e] ----------------
    // 40 field units, exactly 2 per warp; each unit covers all 16 batches.
    #pragma unroll 1
    for (int f = warp; f < F; f += 20) {
        const float* wt = WoutT + f * 1024 + dg * 8;
        ull acc[2][4] = {};
        #pragma unroll
        for (int e4 = 0; e4 < 8; e4++) {
            float4 hv[2];
            #pragma unroll
            for (int jt = 0; jt < 2; jt++)
                hv[jt] = *(const float4*)&h_s[(jg + 8 * jt) * HSTR + f * 32 + e4 * 4];
            #pragma unroll
            for (int ee = 0; ee < 4; ee++) {
                const ulonglong2 wa = __ldg((const ulonglong2*)(wt + (e4 * 4 + ee) * 32));
                const ulonglong2 wb = __ldg((const ulonglong2*)(wt + (e4 * 4 + ee) * 32 + 4));
                #pragma unroll
                for (int jt = 0; jt < 2; jt++) {
                    const ull xd = pack2(((const float*)&hv[jt])[ee]);
                    acc[jt][0] = ffma2(xd, wa.x, acc[jt][0]);
                    acc[jt][1] = ffma2(xd, wa.y, acc[jt][1]);
                    acc[jt][2] = ffma2(xd, wb.x, acc[jt][2]);
                    acc[jt][3] = ffma2(xd, wb.y, acc[jt][3]);
                }
            }
        }
        #pragma unroll
        for (int jt = 0; jt < 2; jt++) {
            *(ulonglong2*)&hoag[(jg + 8 * jt) * HOSTR + f * 32 + dg * 8] =
                make_ulonglong2(acc[jt][0], acc[jt][1]);
            *(ulonglong2*)&hoag[(jg + 8 * jt) * HOSTR + f * 32 + dg * 8 + 4] =
                make_ulonglong2(acc[jt][2], acc[jt][3]);
        }
    }
    __syncthreads();

    // prefetch g chunk 2 (j = 8..15) into the (now free) h region
    if (tid == 0) {
        mbar_expect_tx(mb_g2, 8 * F * F * 4);
        const uint32_t gdst2 = smem_u32(h_s);
        #pragma unroll
        for (int j = 0; j < 8; j++)
            bulk_copy(gdst2 + j * GSTR * 4, g + (b0 + 8 + j) * (F * F), F * F * 4, mb_g2);
    }

    // ---------------- Stage 2: aggr[j][f][d] = sum_gi g[j][f][gi] hout[j][gi][d] ----------------
    // warps 0..15: warp = batch j (in-place aggr-over-hout requires single owner per row).
    if (warp < NB) {
        const int j = warp;
        if (j < 8) mbar_wait(mb_g1, 0);
        else       mbar_wait(mb_g2, 0);
        const float* gj  = (j < 8) ? (g_s + j * GSTR) : (h_s + (j - 8) * GSTR);
        float*       hob = hoag + j * HOSTR;
        const int fg = lane >> 3;
        const int dm = lane & 7;

        ull acc[10][2];
        #pragma unroll
        for (int ft = 0; ft < 10; ft++) { acc[ft][0] = 0ull; acc[ft][1] = 0ull; }

        #pragma unroll 2
        for (int gp = 0; gp < 10; gp++) {          // 4 gi per iter
            ull ho0[4], ho1[4];
            #pragma unroll
            for (int t = 0; t < 4; t++) {
                ho0[t] = *(const ull*)(hob + (gp * 4 + t) * 32 + dm * 2);
                ho1[t] = *(const ull*)(hob + (gp * 4 + t) * 32 + dm * 2 + 16);
            }
            #pragma unroll
            for (int ft = 0; ft < 10; ft++) {
                const float4 g4 = *(const float4*)(gj + (fg + 4 * ft) * F + gp * 4);
                acc[ft][0] = ffma2(pack2(g4.x), ho0[0], acc[ft][0]);
                acc[ft][1] = ffma2(pack2(g4.x), ho1[0], acc[ft][1]);
                acc[ft][0] = ffma2(pack2(g4.y), ho0[1], acc[ft][0]);
                acc[ft][1] = ffma2(pack2(g4.y), ho1[1], acc[ft][1]);
                acc[ft][0] = ffma2(pack2(g4.z), ho0[2], acc[ft][0]);
                acc[ft][1] = ffma2(pack2(g4.z), ho1[2], acc[ft][1]);
                acc[ft][0] = ffma2(pack2(g4.w), ho0[3], acc[ft][0]);
                acc[ft][1] = ffma2(pack2(g4.w), ho1[3], acc[ft][1]);
            }
        }
        #pragma unroll
        for (int ft = 0; ft < 10; ft++) {
            const int f = fg + 4 * ft;
            *(ull*)(hob + f * AFS + dm * 2)      = acc[ft][0];
            *(ull*)(hob + f * AFS + dm * 2 + 16) = acc[ft][1];
        }
    }
    __syncthreads();

    // ---------------- Stage 3: out[j][f][d] = sum_e Win[f][d][e] aggr[j][f][e] + bias ----------------
    const float4 bva = __ldg((const float4*)(bias_p + dg * 8));
    const float4 bvb = __ldg((const float4*)(bias_p + dg * 8 + 4));
    #pragma unroll 1
    for (int f = warp; f < F; f += 20) {
        const float* wt = WinT + f * 1024 + dg * 8;
        ull acc[2][4];
        #pragma unroll
        for (int jt = 0; jt < 2; jt++) {
            acc[jt][0] = packf(bva.x, bva.y);
            acc[jt][1] = packf(bva.z, bva.w);
            acc[jt][2] = packf(bvb.x, bvb.y);
            acc[jt][3] = packf(bvb.z, bvb.w);
        }
        #pragma unroll
        for (int e4 = 0; e4 < 8; e4++) {
            float4 av[2];
            #pragma unroll
            for (int jt = 0; jt < 2; jt++)
                av[jt] = *(const float4*)&hoag[(jg + 8 * jt) * HOSTR + f * AFS + e4 * 4];
            #pragma unroll
            for (int ee = 0; ee < 4; ee++) {
                const ulonglong2 wa = __ldg((const ulonglong2*)(wt + (e4 * 4 + ee) * 32));
                const ulonglong2 wb = __ldg((const ulonglong2*)(wt + (e4 * 4 + ee) * 32 + 4));
                #pragma unroll
                for (int jt = 0; jt < 2; jt++) {
                    const ull xd = pack2(((const float*)&av[jt])[ee]);
                    acc[jt][0] = ffma2(xd, wa.x, acc[jt][0]);
                    acc[jt][1] = ffma2(xd, wa.y, acc[jt][1]);
                    acc[jt][2] = ffma2(xd, wb.x, acc[jt][2]);
                    acc[jt][3] = ffma2(xd, wb.y, acc[jt][3]);
                }
            }
        }
        #pragma unroll
        for (int jt = 0; jt < 2; jt++) {
            const int j = jg + 8 * jt;
            *(ulonglong2*)&out[(b0 + j) * FD + f * 32 + dg * 8] =
                make_ulonglong2(acc[jt][0], acc[jt][1]);
            *(ulonglong2*)&out[(b0 + j) * FD + f * 32 + dg * 8 + 4] =
                make_ulonglong2(acc[jt][2], acc[jt][3]);
        }
    }
}

extern "C" void kernel_launch(void* const* d_in, const int* in_sizes, int n_in,
                              void* d_out, int out_size)
{
    (void)in_sizes; (void)n_in; (void)out_size;
    const float* g     = (const float*)d_in[0];
    const float* h     = (const float*)d_in[1];
    const float* W_in  = (const float*)d_in[2];
    const float* W_out = (const float*)d_in[3];
    const float* bias  = (const float*)d_in[4];
    float* out = (float*)d_out;

    cudaFuncSetAttribute(graphlayer_kernel,
                         cudaFuncAttributeMaxDynamicSharedMemorySize, SMEM_BYTES);

    transposeW_kernel<<<80, 1024>>>(W_in, W_out);
    graphlayer_kernel<<<GRID, NTHREADS, SMEM_BYTES>>>(g, h, bias, out);
}